// round 1
// baseline (speedup 1.0000x reference)
#include <cuda_runtime.h>
#include <math.h>

// Problem constants (fixed shapes from reference)
static constexpr int NN  = 20000;   // nodes
static constexpr int EE  = 320000;  // edges
static constexpr int GG  = 256;     // graphs
static constexpr int INF = 128;     // input dim
static constexpr int DD  = 256;     // hidden dim
static constexpr int PP  = 16;      // prototypes
#define EPSV 1e-7f
#define TEMPV 0.2f

// Output element offsets (float32): KL, NCE, sim[G,P], node_bern[N], edge_bern[E],
// data_sim[G,G], subgraph_embs[G,D], node_embs[N,D]
static constexpr size_t O_KL  = 0;
static constexpr size_t O_NCE = 1;
static constexpr size_t O_SIM = 2;
static constexpr size_t O_NB  = O_SIM + (size_t)GG*PP;     // 4098
static constexpr size_t O_EB  = O_NB  + NN;                // 24098
static constexpr size_t O_DS  = O_EB  + EE;                // 344098
static constexpr size_t O_SE  = O_DS  + (size_t)GG*GG;     // 409634
static constexpr size_t O_NE  = O_SE  + (size_t)GG*DD;     // 475170

// -------- device scratch (no runtime allocation allowed) --------
__device__ __align__(16) float g_agg[(size_t)NN*DD];
__device__ __align__(16) float g_h1 [(size_t)NN*DD];
__device__ __align__(16) float g_h2 [(size_t)NN*DD];   // node_embs scratch
__device__ __align__(16) float g_hid[(size_t)NN*DD];   // mlp hidden / pass2 h2
__device__ __align__(16) float g_x2 [(size_t)NN*INF];
__device__ __align__(16) float g_gemb[(size_t)GG*DD];
__device__ __align__(16) float g_semb[(size_t)GG*DD];
__device__ float g_pnorm[PP];
__device__ float g_gnorm[GG];
__device__ float g_contrib[PP*DD];
__device__ float g_nb[NN];
__device__ int   g_assign[GG];
__device__ int   g_nassign[NN];
__device__ float g_acc[4];

__device__ __forceinline__ float warp_sum(float v) {
#pragma unroll
    for (int o = 16; o > 0; o >>= 1) v += __shfl_down_sync(0xffffffffu, v, o);
    return __shfl_sync(0xffffffffu, v, 0);
}

// -------- elementwise / memory kernels --------
__global__ void zero_k(float* p, int n) {
    int i = blockIdx.x * blockDim.x + threadIdx.x;
    if (i < n) p[i] = 0.f;
}

__global__ void copy4_k(float4* d, const float4* s, int n4) {
    int i = blockIdx.x * blockDim.x + threadIdx.x;
    if (i < n4) d[i] = s[i];
}

__global__ void copyf_k(float* d, const float* s, int n) {
    int i = blockIdx.x * blockDim.x + threadIdx.x;
    if (i < n) d[i] = s[i];
}

// x2 = x * node_bern (row broadcast), vectorized (INF=128 divisible by 4)
__global__ void scale_rows_k(float4* d, const float4* s, const float* nb, int n4) {
    int i = blockIdx.x * blockDim.x + threadIdx.x;
    if (i >= n4) return;
    int row = i / (INF / 4);
    float w = nb[row];
    float4 v = s[i];
    v.x *= w; v.y *= w; v.z *= w; v.w *= w;
    d[i] = v;
}

// -------- graph message passing: agg[dst] += h[src] * (eb?) --------
__global__ void scatter_k(const float* __restrict__ h, const int* __restrict__ src,
                          const int* __restrict__ dst, const float* __restrict__ eb,
                          float* __restrict__ agg, int D) {
    int C = D / 4;
    int t = blockIdx.x * blockDim.x + threadIdx.x;
    if (t >= EE * C) return;
    int e = t / C, c = t % C;
    float4 v = *(const float4*)(h + (size_t)src[e] * D + c * 4);
    float w = eb ? eb[e] : 1.f;
    float* p = agg + (size_t)dst[e] * D + c * 4;
    atomicAdd(p + 0, v.x * w);
    atomicAdd(p + 1, v.y * w);
    atomicAdd(p + 2, v.z * w);
    atomicAdd(p + 3, v.w * w);
}

// graph pooling: g[batch[n]] += h[n]
__global__ void pool_k(const float* __restrict__ h, const int* __restrict__ batch,
                       float* __restrict__ g) {
    const int C = DD / 4;
    int t = blockIdx.x * blockDim.x + threadIdx.x;
    if (t >= NN * C) return;
    int n = t / C, c = t % C;
    float4 v = *(const float4*)(h + (size_t)n * DD + c * 4);
    float* p = g + (size_t)batch[n] * DD + c * 4;
    atomicAdd(p + 0, v.x);
    atomicAdd(p + 1, v.y);
    atomicAdd(p + 2, v.z);
    atomicAdd(p + 3, v.w);
}

// -------- fp32 GEMM: C[M,Nout] = relu(A[M,K] @ W[K,Nout] + bias + rowExtra[rowIdx[m]]) --------
#define BM 64
#define BN 64
#define BK 16
__global__ void gemm_k(const float* __restrict__ A, const float* __restrict__ W,
                       const float* __restrict__ bias, float* __restrict__ C,
                       int M, int K, int Nout,
                       const float* __restrict__ rowExtra, const int* __restrict__ rowIdx,
                       int doRelu) {
    __shared__ float As[BK][BM + 1];
    __shared__ float Ws[BK][BN];
    int bm = blockIdx.y * BM;
    int bn = blockIdx.x * BN;
    int tid = threadIdx.x;
    int tx = tid % 16, ty = tid / 16;
    float acc[4][4] = {};
    for (int k0 = 0; k0 < K; k0 += BK) {
#pragma unroll
        for (int i = 0; i < 4; i++) {
            int idx = tid + i * 256;
            int r = idx / BK, c = idx % BK;
            int gr = bm + r;
            As[c][r] = (gr < M) ? A[(size_t)gr * K + k0 + c] : 0.f;
        }
#pragma unroll
        for (int i = 0; i < 4; i++) {
            int idx = tid + i * 256;
            int r = idx / BN, c = idx % BN;
            Ws[r][c] = W[(size_t)(k0 + r) * Nout + bn + c];
        }
        __syncthreads();
#pragma unroll
        for (int kk = 0; kk < BK; kk++) {
            float a[4], b[4];
#pragma unroll
            for (int i = 0; i < 4; i++) a[i] = As[kk][ty * 4 + i];
#pragma unroll
            for (int j = 0; j < 4; j++) b[j] = Ws[kk][tx * 4 + j];
#pragma unroll
            for (int i = 0; i < 4; i++)
#pragma unroll
                for (int j = 0; j < 4; j++) acc[i][j] += a[i] * b[j];
        }
        __syncthreads();
    }
#pragma unroll
    for (int i = 0; i < 4; i++) {
        int row = bm + ty * 4 + i;
        if (row >= M) continue;
        const float* ex = rowExtra ? rowExtra + (size_t)rowIdx[row] * Nout : nullptr;
#pragma unroll
        for (int j = 0; j < 4; j++) {
            int col = bn + tx * 4 + j;
            float v = acc[i][j] + bias[col];
            if (ex) v += ex[col];
            if (doRelu) v = fmaxf(v, 0.f);
            C[(size_t)row * Nout + col] = v;
        }
    }
}

// -------- cosine / prototype kernels --------
// per-row L2 norm with zero->EPS fixup, rows of length DD, one warp per row
__global__ void rownorm_k(const float* __restrict__ v, float* __restrict__ out) {
    int r = blockIdx.x, lane = threadIdx.x;
    float s = 0.f;
#pragma unroll
    for (int q = 0; q < 8; q++) {
        float e = v[(size_t)r * DD + lane + q * 32];
        s += e * e;
    }
    s = warp_sum(s);
    float n = sqrtf(s);
    if (n == 0.f) n = EPSV;
    if (lane == 0) out[r] = n;
}

__global__ void cos_argmax_k(const float* __restrict__ gemb, const float* __restrict__ proto,
                             const float* __restrict__ pnorm, int* __restrict__ assign) {
    int g = blockIdx.x, lane = threadIdx.x;
    float ge[8];
    float ns = 0.f;
#pragma unroll
    for (int q = 0; q < 8; q++) {
        ge[q] = gemb[(size_t)g * DD + lane + q * 32];
        ns += ge[q] * ge[q];
    }
    ns = warp_sum(ns);
    float nrm = sqrtf(ns);
    if (nrm == 0.f) nrm = EPSV;
    float best = -1e30f;
    int bi = 0;
    for (int p = 0; p < PP; p++) {
        float d = 0.f;
#pragma unroll
        for (int q = 0; q < 8; q++) d += ge[q] * proto[(size_t)p * DD + lane + q * 32];
        d = warp_sum(d);
        float sim = d / (nrm * pnorm[p]);
        if (sim > best) { best = sim; bi = p; }
    }
    if (lane == 0) assign[g] = bi;
}

__global__ void nassign_k(const int* __restrict__ batch, const int* __restrict__ assign,
                          int* __restrict__ nassign) {
    int i = blockIdx.x * blockDim.x + threadIdx.x;
    if (i < NN) nassign[i] = assign[batch[i]];
}

// contrib[p,:] = prototypes[p,:] @ Wm1[DD: , :]
__global__ void contrib_k(const float* __restrict__ proto, const float* __restrict__ Wm1,
                          float* __restrict__ contrib) {
    __shared__ float pr[DD];
    int p = blockIdx.x, tid = threadIdx.x;
    pr[tid] = proto[(size_t)p * DD + tid];
    __syncthreads();
    float a = 0.f;
    for (int k = 0; k < DD; k++) a += pr[k] * Wm1[(size_t)(DD + k) * DD + tid];
    contrib[(size_t)p * DD + tid] = a;
}

// node_prob -> sigmoid; one warp per node
__global__ void nodeprob_k(const float* __restrict__ hid, const float* __restrict__ Wm2,
                           const float* __restrict__ bm2, float* __restrict__ nb,
                           float* __restrict__ nbout) {
    int w = (blockIdx.x * blockDim.x + threadIdx.x) >> 5;
    int lane = threadIdx.x & 31;
    if (w >= NN) return;
    float d = 0.f;
#pragma unroll
    for (int q = 0; q < 8; q++) {
        int c = lane + q * 32;
        d += hid[(size_t)w * DD + c] * Wm2[c];
    }
    d = warp_sum(d);
    float s = 1.f / (1.f + expf(-(d + bm2[0])));
    if (lane == 0) { nb[w] = s; nbout[w] = s; }
}

__global__ void edgebern_k(const float* __restrict__ nb, const int* __restrict__ src,
                           const int* __restrict__ dst, float* __restrict__ out) {
    int i = blockIdx.x * blockDim.x + threadIdx.x;
    if (i < EE) out[i] = nb[src[i]] * nb[dst[i]];
}

// KL sum: term = p*log(p/r + eps) + (1-p)*log((1-p)/(1-r+eps) + eps)
__global__ void kl_k(const float* __restrict__ p, int n, float r, float* __restrict__ slot) {
    float s = 0.f;
    for (int i = blockIdx.x * blockDim.x + threadIdx.x; i < n; i += gridDim.x * blockDim.x) {
        float v = p[i];
        s += v * logf(v / r + EPSV) + (1.f - v) * logf((1.f - v) / (1.f - r + EPSV) + EPSV);
    }
    __shared__ float sh[32];
#pragma unroll
    for (int o = 16; o > 0; o >>= 1) s += __shfl_down_sync(0xffffffffu, s, o);
    if ((threadIdx.x & 31) == 0) sh[threadIdx.x >> 5] = s;
    __syncthreads();
    if (threadIdx.x < 32) {
        float t = (threadIdx.x < (blockDim.x >> 5)) ? sh[threadIdx.x] : 0.f;
#pragma unroll
        for (int o = 16; o > 0; o >>= 1) t += __shfl_down_sync(0xffffffffu, t, o);
        if (threadIdx.x == 0) atomicAdd(slot, t);
    }
}

// similarity (written to out) + per-graph NCE term accumulated
__global__ void sim_nce_k(const float* __restrict__ semb, const float* __restrict__ gnorm,
                          const float* __restrict__ proto, const float* __restrict__ pnorm,
                          float* __restrict__ simout, float* __restrict__ acc) {
    int g = blockIdx.x, lane = threadIdx.x;
    float ge[8];
#pragma unroll
    for (int q = 0; q < 8; q++) ge[q] = semb[(size_t)g * DD + lane + q * 32];
    float nrm = gnorm[g];
    float best = -1e30f, pos = 0.f, sum = 0.f;
    for (int p = 0; p < PP; p++) {
        float d = 0.f;
#pragma unroll
        for (int q = 0; q < 8; q++) d += ge[q] * proto[(size_t)p * DD + lane + q * 32];
        d = warp_sum(d);
        float sim = d / (nrm * pnorm[p]);
        if (lane == 0) simout[(size_t)g * PP + p] = sim;
        float se = expf(sim / TEMPV);
        sum += se;
        if (sim > best) { best = sim; pos = se; }
    }
    if (lane == 0) atomicAdd(&acc[2], -logf(pos / (sum - pos)));
}

// data_sim[i,j] = cos(semb_i, semb_j)
__global__ void datasim_k(const float* __restrict__ semb, const float* __restrict__ gnorm,
                          float* __restrict__ out) {
    __shared__ float ri[DD];
    int i = blockIdx.x, tid = threadIdx.x, lane = tid & 31, w = tid >> 5;
    ri[tid] = semb[(size_t)i * DD + tid];
    __syncthreads();
    float ni = gnorm[i];
    for (int j = w; j < GG; j += 8) {
        float d = 0.f;
#pragma unroll
        for (int q = 0; q < 8; q++) {
            int c = lane + q * 32;
            d += ri[c] * semb[(size_t)j * DD + c];
        }
        d = warp_sum(d);
        if (lane == 0) out[(size_t)i * GG + j] = d / (ni * gnorm[j]);
    }
}

__global__ void finalize_k(const float* __restrict__ acc, float* __restrict__ out) {
    if (threadIdx.x == 0) {
        out[O_KL]  = acc[0] / (float)NN + acc[1] / (float)EE;
        out[O_NCE] = acc[2] / (float)GG;
    }
}

// =====================================================================
extern "C" void kernel_launch(void* const* d_in, const int* in_sizes, int n_in,
                              void* d_out, int out_size) {
    const float* x    = (const float*)d_in[0];
    const int*   ei   = (const int*)d_in[1];
    const int*   bat  = (const int*)d_in[2];
    const float* W1   = (const float*)d_in[3];
    const float* b1   = (const float*)d_in[4];
    const float* W2   = (const float*)d_in[5];
    const float* b2   = (const float*)d_in[6];
    const float* Wm1  = (const float*)d_in[7];
    const float* bm1  = (const float*)d_in[8];
    const float* Wm2  = (const float*)d_in[9];
    const float* bm2  = (const float*)d_in[10];
    const float* prot = (const float*)d_in[11];
    float* out = (float*)d_out;

    const int* src = ei;
    const int* dst = ei + EE;

    float *agg, *h1, *h2, *hid, *x2, *gemb, *semb, *pnorm, *gnorm, *contrib, *nb, *acc;
    int *assign, *nassign;
    cudaGetSymbolAddress((void**)&agg, g_agg);
    cudaGetSymbolAddress((void**)&h1, g_h1);
    cudaGetSymbolAddress((void**)&h2, g_h2);
    cudaGetSymbolAddress((void**)&hid, g_hid);
    cudaGetSymbolAddress((void**)&x2, g_x2);
    cudaGetSymbolAddress((void**)&gemb, g_gemb);
    cudaGetSymbolAddress((void**)&semb, g_semb);
    cudaGetSymbolAddress((void**)&pnorm, g_pnorm);
    cudaGetSymbolAddress((void**)&gnorm, g_gnorm);
    cudaGetSymbolAddress((void**)&contrib, g_contrib);
    cudaGetSymbolAddress((void**)&nb, g_nb);
    cudaGetSymbolAddress((void**)&acc, g_acc);
    cudaGetSymbolAddress((void**)&assign, g_assign);
    cudaGetSymbolAddress((void**)&nassign, g_nassign);

    const int T = 256;
    auto blks = [](long n, int t) { return (int)((n + t - 1) / t); };

    // accumulators
    zero_k<<<1, 32>>>(acc, 4);

    // ---- pass 1, conv 1 (K = INF) ----
    copy4_k<<<blks((long)NN * INF / 4, T), T>>>((float4*)agg, (const float4*)x, NN * INF / 4);
    scatter_k<<<blks((long)EE * (INF / 4), T), T>>>(x, src, dst, nullptr, agg, INF);
    {
        dim3 g(DD / BN, (NN + BM - 1) / BM);
        gemm_k<<<g, 256>>>(agg, W1, b1, h1, NN, INF, DD, nullptr, nullptr, 1);
    }
    // ---- pass 1, conv 2 (K = DD) ----
    copy4_k<<<blks((long)NN * DD / 4, T), T>>>((float4*)agg, (const float4*)h1, NN * DD / 4);
    scatter_k<<<blks((long)EE * (DD / 4), T), T>>>(h1, src, dst, nullptr, agg, DD);
    {
        dim3 g(DD / BN, (NN + BM - 1) / BM);
        gemm_k<<<g, 256>>>(agg, W2, b2, h2, NN, DD, DD, nullptr, nullptr, 1);
    }
    // graph pooling + node_embs output
    zero_k<<<blks(GG * DD, T), T>>>(gemb, GG * DD);
    pool_k<<<blks((long)NN * (DD / 4), T), T>>>(h2, bat, gemb);
    copyf_k<<<blks((long)NN * DD, T), T>>>(out + O_NE, h2, NN * DD);

    // prototype assignment
    rownorm_k<<<PP, 32>>>(prot, pnorm);
    cos_argmax_k<<<GG, 32>>>(gemb, prot, pnorm, assign);
    nassign_k<<<blks(NN, T), T>>>(bat, assign, nassign);

    // MLP: hidden = relu(h2 @ Wm1[:D] + bm1 + contrib[assign[batch]])
    contrib_k<<<PP, DD>>>(prot, Wm1, contrib);
    {
        dim3 g(DD / BN, (NN + BM - 1) / BM);
        gemm_k<<<g, 256>>>(h2, Wm1, bm1, hid, NN, DD, DD, contrib, nassign, 1);
    }
    nodeprob_k<<<blks((long)NN * 32, T), T>>>(hid, Wm2, bm2, nb, out + O_NB);
    edgebern_k<<<blks(EE, T), T>>>(nb, src, dst, out + O_EB);

    // KL terms
    kl_k<<<512, T>>>(nb, NN, 0.5f, acc + 0);
    kl_k<<<1024, T>>>(out + O_EB, EE, 0.25f, acc + 1);

    // ---- pass 2 (attenuated) ----
    scale_rows_k<<<blks((long)NN * INF / 4, T), T>>>((float4*)x2, (const float4*)x, nb, NN * INF / 4);
    copy4_k<<<blks((long)NN * INF / 4, T), T>>>((float4*)agg, (const float4*)x2, NN * INF / 4);
    scatter_k<<<blks((long)EE * (INF / 4), T), T>>>(x2, src, dst, out + O_EB, agg, INF);
    {
        dim3 g(DD / BN, (NN + BM - 1) / BM);
        gemm_k<<<g, 256>>>(agg, W1, b1, h1, NN, INF, DD, nullptr, nullptr, 1);
    }
    copy4_k<<<blks((long)NN * DD / 4, T), T>>>((float4*)agg, (const float4*)h1, NN * DD / 4);
    scatter_k<<<blks((long)EE * (DD / 4), T), T>>>(h1, src, dst, out + O_EB, agg, DD);
    {
        dim3 g(DD / BN, (NN + BM - 1) / BM);
        gemm_k<<<g, 256>>>(agg, W2, b2, hid, NN, DD, DD, nullptr, nullptr, 1);
    }
    zero_k<<<blks(GG * DD, T), T>>>(semb, GG * DD);
    pool_k<<<blks((long)NN * (DD / 4), T), T>>>(hid, bat, semb);
    copyf_k<<<blks(GG * DD, T), T>>>(out + O_SE, semb, GG * DD);

    // similarity + NCE, data_sim
    rownorm_k<<<GG, 32>>>(semb, gnorm);
    sim_nce_k<<<GG, 32>>>(semb, gnorm, prot, pnorm, out + O_SIM, acc);
    datasim_k<<<GG, DD>>>(semb, gnorm, out + O_DS);

    finalize_k<<<1, 32>>>(acc, out);
}

// round 4
// speedup vs baseline: 1.7274x; 1.7274x over previous
#include <cuda_runtime.h>
#include <math.h>

static constexpr int NN  = 20000;
static constexpr int EE  = 320000;
static constexpr int GG  = 256;
static constexpr int INF = 128;
static constexpr int DD  = 256;
static constexpr int PP  = 16;
#define EPSV 1e-7f
#define TEMPV 0.2f

static constexpr size_t O_KL  = 0;
static constexpr size_t O_NCE = 1;
static constexpr size_t O_SIM = 2;
static constexpr size_t O_NB  = O_SIM + (size_t)GG*PP;
static constexpr size_t O_EB  = O_NB  + NN;
static constexpr size_t O_DS  = O_EB  + EE;
static constexpr size_t O_SE  = O_DS  + (size_t)GG*GG;
static constexpr size_t O_NE  = O_SE  + (size_t)GG*DD;
// NOTE: d_out at O_SE/O_NE is only 8-byte aligned. NO float4 access into d_out
// anywhere. Embeddings are computed in 16B-aligned scratch and mirrored out
// with float2 stores.

// -------- device scratch --------
__device__ __align__(16) float g_agg[(size_t)NN*DD];
__device__ __align__(16) float g_h1 [(size_t)NN*DD];
__device__ __align__(16) float g_h2 [(size_t)NN*DD];   // node_embs (aligned master copy)
__device__ __align__(16) float g_hid[(size_t)NN*DD];
__device__ __align__(16) float g_x2 [(size_t)NN*INF];
__device__ __align__(16) float g_gemb[(size_t)GG*DD];
__device__ float g_pnorm[PP];
__device__ float g_gnorm[GG];
__device__ float g_contrib[PP*DD];
__device__ float g_nb[NN];
__device__ int   g_assign[GG];
__device__ int   g_nassign[NN];
__device__ float g_acc[4];
// CSR
__device__ int g_cnt[NN];
__device__ int g_ptr[NN + 1];
__device__ int g_cursor[NN];
__device__ int g_eidx[EE];
__device__ int g_gstart[GG + 1];

__device__ __forceinline__ float warp_sum(float v) {
#pragma unroll
    for (int o = 16; o > 0; o >>= 1) v += __shfl_down_sync(0xffffffffu, v, o);
    return __shfl_sync(0xffffffffu, v, 0);
}

// -------- misc --------
__global__ void zero_f(float* p, int n) {
    int i = blockIdx.x * blockDim.x + threadIdx.x;
    if (i < n) p[i] = 0.f;
}
__global__ void zero_i(int* p, int n) {
    int i = blockIdx.x * blockDim.x + threadIdx.x;
    if (i < n) p[i] = 0;
}
__global__ void copy_i(int* d, const int* s, int n) {
    int i = blockIdx.x * blockDim.x + threadIdx.x;
    if (i < n) d[i] = s[i];
}
// float2 copy — safe for 8B-aligned d_out destinations
__global__ void copy2_k(float2* d, const float2* s, int n2) {
    int i = blockIdx.x * blockDim.x + threadIdx.x;
    if (i < n2) d[i] = s[i];
}

// x2 = x * node_bern
__global__ void scale_rows_k(float4* d, const float4* s, const float* __restrict__ nb, int n4) {
    int i = blockIdx.x * blockDim.x + threadIdx.x;
    if (i >= n4) return;
    float w = nb[i / (INF / 4)];
    float4 v = s[i];
    v.x *= w; v.y *= w; v.z *= w; v.w *= w;
    d[i] = v;
}

// -------- CSR build --------
__global__ void hist_k(const int* __restrict__ dst, int* __restrict__ cnt) {
    int e = blockIdx.x * blockDim.x + threadIdx.x;
    if (e < EE) atomicAdd(&cnt[dst[e]], 1);
}

__global__ void scan_k(const int* __restrict__ cnt, int* __restrict__ ptr, int n) {
    __shared__ int warpsum[32];
    __shared__ int carry;
    int tid = threadIdx.x, lane = tid & 31, w = tid >> 5;
    if (tid == 0) carry = 0;
    __syncthreads();
    for (int base = 0; base < n; base += blockDim.x) {
        int i = base + tid;
        int v = (i < n) ? cnt[i] : 0;
        int s = v;
#pragma unroll
        for (int o = 1; o < 32; o <<= 1) {
            int t = __shfl_up_sync(0xffffffffu, s, o);
            if (lane >= o) s += t;
        }
        if (lane == 31) warpsum[w] = s;
        __syncthreads();
        if (w == 0) {
            int t = warpsum[lane];
#pragma unroll
            for (int o = 1; o < 32; o <<= 1) {
                int u = __shfl_up_sync(0xffffffffu, t, o);
                if (lane >= o) t += u;
            }
            warpsum[lane] = t;
        }
        __syncthreads();
        int excl = s - v + (w ? warpsum[w - 1] : 0) + carry;
        if (i < n) ptr[i] = excl;
        __syncthreads();
        if (tid == blockDim.x - 1) carry = excl + v;
        __syncthreads();
    }
    if (tid == 0) ptr[n] = carry;
}

__global__ void fill_k(const int* __restrict__ dst, int* __restrict__ cursor,
                       int* __restrict__ eidx) {
    int e = blockIdx.x * blockDim.x + threadIdx.x;
    if (e >= EE) return;
    int p = atomicAdd(&cursor[dst[e]], 1);
    eidx[p] = e;
}

__global__ void gstart_k(const int* __restrict__ batch, int* __restrict__ gs) {
    int g = blockIdx.x * blockDim.x + threadIdx.x;
    if (g > GG) return;
    if (g == GG) { gs[GG] = NN; return; }
    int lo = 0, hi = NN;
    while (lo < hi) { int mid = (lo + hi) >> 1; if (batch[mid] < g) lo = mid + 1; else hi = mid; }
    gs[g] = lo;
}

// -------- gather-based GIN aggregation (all pointers are aligned scratch) --------
template <int D>
__global__ void gather_agg_k(const float* __restrict__ h, const int* __restrict__ ptr,
                             const int* __restrict__ eidx, const int* __restrict__ src,
                             const float* __restrict__ eb, float* __restrict__ agg) {
    constexpr int TPN = D / 4;
    constexpr int NPB = 256 / TPN;
    int node = blockIdx.x * NPB + threadIdx.x / TPN;
    int lane = threadIdx.x % TPN;
    if (node >= NN) return;
    float4 acc = *(const float4*)(h + (size_t)node * D + lane * 4);
    int b = ptr[node], e = ptr[node + 1];
    for (int i = b; i < e; i++) {
        int id = eidx[i];
        int s = src[id];
        float w = eb ? eb[id] : 1.f;
        float4 v = *(const float4*)(h + (size_t)s * D + lane * 4);
        acc.x += v.x * w; acc.y += v.y * w; acc.z += v.z * w; acc.w += v.w * w;
    }
    *(float4*)(agg + (size_t)node * D + lane * 4) = acc;
}

// -------- pooling: reads aligned scratch (float4), writes d_out-safe float2 --------
__global__ void pool_g_k(const float* __restrict__ h, const int* __restrict__ gs,
                         float* __restrict__ gout) {
    int g = blockIdx.x, lane = threadIdx.x;  // 64 threads, one float4 each
    float4 acc = make_float4(0.f, 0.f, 0.f, 0.f);
    int b = gs[g], e = gs[g + 1];
    for (int n = b; n < e; n++) {
        float4 v = *(const float4*)(h + (size_t)n * DD + lane * 4);
        acc.x += v.x; acc.y += v.y; acc.z += v.z; acc.w += v.w;
    }
    float* o = gout + (size_t)g * DD + lane * 4;
    *(float2*)(o)     = make_float2(acc.x, acc.y);
    *(float2*)(o + 2) = make_float2(acc.z, acc.w);
}

// -------- fp32 GEMM 128x128x8, 8x8 microtile (A, C are aligned scratch only) --------
#define GBM 128
#define GBN 128
#define GBK 8
__global__ __launch_bounds__(256, 2)
void gemm2_k(const float* __restrict__ A, const float* __restrict__ W,
             const float* __restrict__ bias, float* __restrict__ C,
             int M, int K, int Nout,
             const float* __restrict__ rowExtra, const int* __restrict__ rowIdx,
             int doRelu) {
    __shared__ float As[GBK][GBM];
    __shared__ float Ws[GBK][GBN];
    int bm = blockIdx.y * GBM, bn = blockIdx.x * GBN;
    int tid = threadIdx.x;
    int ar = tid >> 1;
    int ac = (tid & 1) * 4;
    int wr = tid >> 5;
    int wc = (tid & 31) * 4;
    int tx = tid % 16, ty = tid / 16;
    float acc[8][8] = {};
    for (int k0 = 0; k0 < K; k0 += GBK) {
        int grow = bm + ar;
        float4 av = (grow < M) ? *(const float4*)(A + (size_t)grow * K + k0 + ac)
                               : make_float4(0.f, 0.f, 0.f, 0.f);
        As[ac + 0][ar] = av.x; As[ac + 1][ar] = av.y;
        As[ac + 2][ar] = av.z; As[ac + 3][ar] = av.w;
        *(float4*)(&Ws[wr][wc]) = *(const float4*)(W + (size_t)(k0 + wr) * Nout + bn + wc);
        __syncthreads();
#pragma unroll
        for (int kk = 0; kk < GBK; kk++) {
            float a[8], b[8];
            *(float4*)(a)     = *(const float4*)(&As[kk][ty * 4]);
            *(float4*)(a + 4) = *(const float4*)(&As[kk][64 + ty * 4]);
            *(float4*)(b)     = *(const float4*)(&Ws[kk][tx * 4]);
            *(float4*)(b + 4) = *(const float4*)(&Ws[kk][64 + tx * 4]);
#pragma unroll
            for (int i = 0; i < 8; i++)
#pragma unroll
                for (int j = 0; j < 8; j++) acc[i][j] += a[i] * b[j];
        }
        __syncthreads();
    }
#pragma unroll
    for (int i = 0; i < 8; i++) {
        int row = bm + (i < 4 ? ty * 4 + i : 64 + ty * 4 + i - 4);
        if (row >= M) continue;
        const float* ex = rowExtra ? rowExtra + (size_t)rowIdx[row] * Nout : nullptr;
#pragma unroll
        for (int j = 0; j < 8; j++) {
            int col = bn + (j < 4 ? tx * 4 + j : 64 + tx * 4 + j - 4);
            float v = acc[i][j] + bias[col];
            if (ex) v += ex[col];
            if (doRelu) v = fmaxf(v, 0.f);
            C[(size_t)row * Nout + col] = v;
        }
    }
}

// -------- cosine / prototype kernels (scalar loads — d_out-safe) --------
__global__ void rownorm_k(const float* __restrict__ v, float* __restrict__ out) {
    int r = blockIdx.x, lane = threadIdx.x;
    float s = 0.f;
#pragma unroll
    for (int q = 0; q < 8; q++) {
        float e = v[(size_t)r * DD + lane + q * 32];
        s += e * e;
    }
    s = warp_sum(s);
    float n = sqrtf(s);
    if (n == 0.f) n = EPSV;
    if (lane == 0) out[r] = n;
}

__global__ void cos_argmax_k(const float* __restrict__ gemb, const float* __restrict__ proto,
                             const float* __restrict__ pnorm, int* __restrict__ assign) {
    int g = blockIdx.x, lane = threadIdx.x;
    float ge[8];
    float ns = 0.f;
#pragma unroll
    for (int q = 0; q < 8; q++) {
        ge[q] = gemb[(size_t)g * DD + lane + q * 32];
        ns += ge[q] * ge[q];
    }
    ns = warp_sum(ns);
    float nrm = sqrtf(ns);
    if (nrm == 0.f) nrm = EPSV;
    float best = -1e30f;
    int bi = 0;
    for (int p = 0; p < PP; p++) {
        float d = 0.f;
#pragma unroll
        for (int q = 0; q < 8; q++) d += ge[q] * proto[(size_t)p * DD + lane + q * 32];
        d = warp_sum(d);
        float sim = d / (nrm * pnorm[p]);
        if (sim > best) { best = sim; bi = p; }
    }
    if (lane == 0) assign[g] = bi;
}

__global__ void nassign_k(const int* __restrict__ batch, const int* __restrict__ assign,
                          int* __restrict__ nassign) {
    int i = blockIdx.x * blockDim.x + threadIdx.x;
    if (i < NN) nassign[i] = assign[batch[i]];
}

__global__ void contrib_k(const float* __restrict__ proto, const float* __restrict__ Wm1,
                          float* __restrict__ contrib) {
    __shared__ float pr[DD];
    int p = blockIdx.x, tid = threadIdx.x;
    pr[tid] = proto[(size_t)p * DD + tid];
    __syncthreads();
    float a = 0.f;
    for (int k = 0; k < DD; k++) a += pr[k] * Wm1[(size_t)(DD + k) * DD + tid];
    contrib[(size_t)p * DD + tid] = a;
}

__global__ void nodeprob_k(const float* __restrict__ hid, const float* __restrict__ Wm2,
                           const float* __restrict__ bm2, float* __restrict__ nb,
                           float* __restrict__ nbout) {
    int w = (blockIdx.x * blockDim.x + threadIdx.x) >> 5;
    int lane = threadIdx.x & 31;
    if (w >= NN) return;
    float d = 0.f;
#pragma unroll
    for (int q = 0; q < 8; q++) {
        int c = lane + q * 32;
        d += hid[(size_t)w * DD + c] * Wm2[c];
    }
    d = warp_sum(d);
    float s = 1.f / (1.f + expf(-(d + bm2[0])));
    if (lane == 0) { nb[w] = s; nbout[w] = s; }
}

__global__ void edgebern_k(const float* __restrict__ nb, const int* __restrict__ src,
                           const int* __restrict__ dst, float* __restrict__ out) {
    int i = blockIdx.x * blockDim.x + threadIdx.x;
    if (i < EE) out[i] = nb[src[i]] * nb[dst[i]];
}

__global__ void kl_k(const float* __restrict__ p, int n, float r, float* __restrict__ slot) {
    float s = 0.f;
    for (int i = blockIdx.x * blockDim.x + threadIdx.x; i < n; i += gridDim.x * blockDim.x) {
        float v = p[i];
        s += v * logf(v / r + EPSV) + (1.f - v) * logf((1.f - v) / (1.f - r + EPSV) + EPSV);
    }
    __shared__ float sh[32];
#pragma unroll
    for (int o = 16; o > 0; o >>= 1) s += __shfl_down_sync(0xffffffffu, s, o);
    if ((threadIdx.x & 31) == 0) sh[threadIdx.x >> 5] = s;
    __syncthreads();
    if (threadIdx.x < 32) {
        float t = (threadIdx.x < (blockDim.x >> 5)) ? sh[threadIdx.x] : 0.f;
#pragma unroll
        for (int o = 16; o > 0; o >>= 1) t += __shfl_down_sync(0xffffffffu, t, o);
        if (threadIdx.x == 0) atomicAdd(slot, t);
    }
}

__global__ void sim_nce_k(const float* __restrict__ semb, const float* __restrict__ gnorm,
                          const float* __restrict__ proto, const float* __restrict__ pnorm,
                          float* __restrict__ simout, float* __restrict__ acc) {
    int g = blockIdx.x, lane = threadIdx.x;
    float ge[8];
#pragma unroll
    for (int q = 0; q < 8; q++) ge[q] = semb[(size_t)g * DD + lane + q * 32];
    float nrm = gnorm[g];
    float best = -1e30f, pos = 0.f, sum = 0.f;
    for (int p = 0; p < PP; p++) {
        float d = 0.f;
#pragma unroll
        for (int q = 0; q < 8; q++) d += ge[q] * proto[(size_t)p * DD + lane + q * 32];
        d = warp_sum(d);
        float sim = d / (nrm * pnorm[p]);
        if (lane == 0) simout[(size_t)g * PP + p] = sim;
        float se = expf(sim / TEMPV);
        sum += se;
        if (sim > best) { best = sim; pos = se; }
    }
    if (lane == 0) atomicAdd(&acc[2], -logf(pos / (sum - pos)));
}

__global__ void datasim_k(const float* __restrict__ semb, const float* __restrict__ gnorm,
                          float* __restrict__ out) {
    __shared__ float ri[DD];
    int i = blockIdx.x, tid = threadIdx.x, lane = tid & 31, w = tid >> 5;
    ri[tid] = semb[(size_t)i * DD + tid];
    __syncthreads();
    float ni = gnorm[i];
    for (int j = w; j < GG; j += 8) {
        float d = 0.f;
#pragma unroll
        for (int q = 0; q < 8; q++) {
            int c = lane + q * 32;
            d += ri[c] * semb[(size_t)j * DD + c];
        }
        d = warp_sum(d);
        if (lane == 0) out[(size_t)i * GG + j] = d / (ni * gnorm[j]);
    }
}

__global__ void finalize_k(const float* __restrict__ acc, float* __restrict__ out) {
    if (threadIdx.x == 0) {
        out[O_KL]  = acc[0] / (float)NN + acc[1] / (float)EE;
        out[O_NCE] = acc[2] / (float)GG;
    }
}

// =====================================================================
extern "C" void kernel_launch(void* const* d_in, const int* in_sizes, int n_in,
                              void* d_out, int out_size) {
    const float* x    = (const float*)d_in[0];
    const int*   ei   = (const int*)d_in[1];
    const int*   bat  = (const int*)d_in[2];
    const float* W1   = (const float*)d_in[3];
    const float* b1   = (const float*)d_in[4];
    const float* W2   = (const float*)d_in[5];
    const float* b2   = (const float*)d_in[6];
    const float* Wm1  = (const float*)d_in[7];
    const float* bm1  = (const float*)d_in[8];
    const float* Wm2  = (const float*)d_in[9];
    const float* bm2  = (const float*)d_in[10];
    const float* prot = (const float*)d_in[11];
    float* out = (float*)d_out;

    const int* src = ei;
    const int* dst = ei + EE;

    float *agg, *h1, *h2, *hid, *x2, *gemb, *pnorm, *gnorm, *contrib, *nb, *acc;
    int *assign, *nassign, *cnt, *ptr, *cursor, *eidx, *gstart;
    cudaGetSymbolAddress((void**)&agg, g_agg);
    cudaGetSymbolAddress((void**)&h1, g_h1);
    cudaGetSymbolAddress((void**)&h2, g_h2);
    cudaGetSymbolAddress((void**)&hid, g_hid);
    cudaGetSymbolAddress((void**)&x2, g_x2);
    cudaGetSymbolAddress((void**)&gemb, g_gemb);
    cudaGetSymbolAddress((void**)&pnorm, g_pnorm);
    cudaGetSymbolAddress((void**)&gnorm, g_gnorm);
    cudaGetSymbolAddress((void**)&contrib, g_contrib);
    cudaGetSymbolAddress((void**)&nb, g_nb);
    cudaGetSymbolAddress((void**)&acc, g_acc);
    cudaGetSymbolAddress((void**)&assign, g_assign);
    cudaGetSymbolAddress((void**)&nassign, g_nassign);
    cudaGetSymbolAddress((void**)&cnt, g_cnt);
    cudaGetSymbolAddress((void**)&ptr, g_ptr);
    cudaGetSymbolAddress((void**)&cursor, g_cursor);
    cudaGetSymbolAddress((void**)&eidx, g_eidx);
    cudaGetSymbolAddress((void**)&gstart, g_gstart);

    const int T = 256;
    auto blks = [](long n, int t) { return (int)((n + t - 1) / t); };

    zero_f<<<1, 32>>>(acc, 4);

    // ---- CSR build (by dst) ----
    zero_i<<<blks(NN, T), T>>>(cnt, NN);
    hist_k<<<blks(EE, T), T>>>(dst, cnt);
    scan_k<<<1, 1024>>>(cnt, ptr, NN);
    copy_i<<<blks(NN, T), T>>>(cursor, ptr, NN);
    fill_k<<<blks(EE, T), T>>>(dst, cursor, eidx);
    gstart_k<<<1, GG + 1>>>(bat, gstart);

    dim3 gg(DD / GBN, (NN + GBM - 1) / GBM);

    // ---- pass 1 ----
    gather_agg_k<INF><<<blks(NN, 8), 256>>>(x, ptr, eidx, src, nullptr, agg);
    gemm2_k<<<gg, 256>>>(agg, W1, b1, h1, NN, INF, DD, nullptr, nullptr, 1);
    gather_agg_k<DD><<<blks(NN, 4), 256>>>(h1, ptr, eidx, src, nullptr, agg);
    gemm2_k<<<gg, 256>>>(agg, W2, b2, h2, NN, DD, DD, nullptr, nullptr, 1);  // node_embs (scratch)
    copy2_k<<<blks((long)NN * DD / 2, T), T>>>((float2*)(out + O_NE), (const float2*)h2, NN * DD / 2);
    pool_g_k<<<GG, 64>>>(h2, gstart, gemb);

    // prototype assignment
    rownorm_k<<<PP, 32>>>(prot, pnorm);
    cos_argmax_k<<<GG, 32>>>(gemb, prot, pnorm, assign);
    nassign_k<<<blks(NN, T), T>>>(bat, assign, nassign);

    // MLP (reads aligned h2, not d_out)
    contrib_k<<<PP, DD>>>(prot, Wm1, contrib);
    gemm2_k<<<gg, 256>>>(h2, Wm1, bm1, hid, NN, DD, DD, contrib, nassign, 1);
    nodeprob_k<<<blks((long)NN * 32, T), T>>>(hid, Wm2, bm2, nb, out + O_NB);
    edgebern_k<<<blks(EE, T), T>>>(nb, src, dst, out + O_EB);

    kl_k<<<512, T>>>(nb, NN, 0.5f, acc + 0);
    kl_k<<<1024, T>>>(out + O_EB, EE, 0.25f, acc + 1);

    // ---- pass 2 (attenuated) ----
    scale_rows_k<<<blks((long)NN * INF / 4, T), T>>>((float4*)x2, (const float4*)x, nb, NN * INF / 4);
    gather_agg_k<INF><<<blks(NN, 8), 256>>>(x2, ptr, eidx, src, out + O_EB, agg);
    gemm2_k<<<gg, 256>>>(agg, W1, b1, h1, NN, INF, DD, nullptr, nullptr, 1);
    gather_agg_k<DD><<<blks(NN, 4), 256>>>(h1, ptr, eidx, src, out + O_EB, agg);
    gemm2_k<<<gg, 256>>>(agg, W2, b2, hid, NN, DD, DD, nullptr, nullptr, 1);
    pool_g_k<<<GG, 64>>>(hid, gstart, out + O_SE);  // float2 stores into d_out

    rownorm_k<<<GG, 32>>>(out + O_SE, gnorm);
    sim_nce_k<<<GG, 32>>>(out + O_SE, gnorm, prot, pnorm, out + O_SIM, acc);
    datasim_k<<<GG, DD>>>(out + O_SE, gnorm, out + O_DS);

    finalize_k<<<1, 32>>>(acc, out);
}

// round 5
// speedup vs baseline: 1.7772x; 1.0288x over previous
#include <cuda_runtime.h>
#include <math.h>

static constexpr int NN  = 20000;
static constexpr int EE  = 320000;
static constexpr int GG  = 256;
static constexpr int INF = 128;
static constexpr int DD  = 256;
static constexpr int PP  = 16;
#define EPSV 1e-7f
#define TEMPV 0.2f

static constexpr size_t O_KL  = 0;
static constexpr size_t O_NCE = 1;
static constexpr size_t O_SIM = 2;
static constexpr size_t O_NB  = O_SIM + (size_t)GG*PP;
static constexpr size_t O_EB  = O_NB  + NN;
static constexpr size_t O_DS  = O_EB  + EE;
static constexpr size_t O_SE  = O_DS  + (size_t)GG*GG;
static constexpr size_t O_NE  = O_SE  + (size_t)GG*DD;
// d_out at O_SE/O_NE is only 8-byte aligned: NEVER float4 into d_out.

static constexpr int SCAN_B = (NN + 255) / 256;   // 79

// -------- device scratch --------
__device__ __align__(16) float g_agg[(size_t)NN*DD];
__device__ __align__(16) float g_h1 [(size_t)NN*DD];
__device__ __align__(16) float g_h2 [(size_t)NN*DD];
__device__ __align__(16) float g_hid[(size_t)NN*DD];
__device__ __align__(16) float g_gemb[(size_t)GG*DD];
__device__ float g_pnorm[PP];
__device__ float g_gnorm[GG];
__device__ float g_contrib[PP*DD];
__device__ float g_nb[NN];
__device__ int   g_assign[GG];
__device__ int   g_nassign[NN];
__device__ float g_acc[4];
__device__ int g_cnt[NN];
__device__ int g_ptr[NN + 1];
__device__ int g_cursor[NN];
__device__ int g_eidx[EE];
__device__ int g_gstart[GG + 1];
__device__ int g_bsum[SCAN_B];

__device__ __forceinline__ float warp_sum(float v) {
#pragma unroll
    for (int o = 16; o > 0; o >>= 1) v += __shfl_down_sync(0xffffffffu, v, o);
    return __shfl_sync(0xffffffffu, v, 0);
}

// block-reduce (256 threads) then one atomic
__device__ __forceinline__ void block_atomic_add(float v, float* slot) {
    __shared__ float sh[8];
#pragma unroll
    for (int o = 16; o > 0; o >>= 1) v += __shfl_down_sync(0xffffffffu, v, o);
    if ((threadIdx.x & 31) == 0) sh[threadIdx.x >> 5] = v;
    __syncthreads();
    if (threadIdx.x == 0) {
        float t = 0.f;
#pragma unroll
        for (int q = 0; q < 8; q++) t += sh[q];
        atomicAdd(slot, t);
    }
}

// -------- init: zero cnt, cursor, acc --------
__global__ void zero_misc_k(int* cnt, int* cursor, float* acc) {
    int i = blockIdx.x * blockDim.x + threadIdx.x;
    if (i < NN) { cnt[i] = 0; cursor[i] = 0; }
    if (i < 4) acc[i] = 0.f;
}

// -------- CSR build --------
__global__ void hist_k(const int* __restrict__ dst, int* __restrict__ cnt) {
    int e = blockIdx.x * blockDim.x + threadIdx.x;
    if (e < EE) atomicAdd(&cnt[dst[e]], 1);
}

// per-block exclusive scan of 256-tile, write local prefix + block total
__global__ void scan1_k(const int* __restrict__ cnt, int* __restrict__ ptr,
                        int* __restrict__ bsum) {
    int i = blockIdx.x * 256 + threadIdx.x;
    int lane = threadIdx.x & 31, w = threadIdx.x >> 5;
    int v = (i < NN) ? cnt[i] : 0;
    int s = v;
#pragma unroll
    for (int o = 1; o < 32; o <<= 1) {
        int t = __shfl_up_sync(0xffffffffu, s, o);
        if (lane >= o) s += t;
    }
    __shared__ int ws[8];
    if (lane == 31) ws[w] = s;
    __syncthreads();
    if (threadIdx.x < 8) {
        int t = ws[threadIdx.x];
#pragma unroll
        for (int o = 1; o < 8; o <<= 1) {
            int u = __shfl_up_sync(0xffu, t, o);
            if ((int)threadIdx.x >= o) t += u;
        }
        ws[threadIdx.x] = t;
    }
    __syncthreads();
    int excl = s - v + (w ? ws[w - 1] : 0);
    if (i < NN) ptr[i] = excl;
    if (threadIdx.x == 255) bsum[blockIdx.x] = excl + v;
}

// add cross-block offsets; last block writes ptr[NN]
__global__ void scan2_k(int* __restrict__ ptr, const int* __restrict__ bsum) {
    int b = blockIdx.x;
    float dummy; (void)dummy;
    int partial = 0;
    for (int j = threadIdx.x; j < b; j += 256) partial += bsum[j];
    __shared__ int sh[8];
    int lane = threadIdx.x & 31, w = threadIdx.x >> 5;
#pragma unroll
    for (int o = 16; o > 0; o >>= 1) partial += __shfl_down_sync(0xffffffffu, partial, o);
    if (lane == 0) sh[w] = partial;
    __syncthreads();
    __shared__ int off;
    if (threadIdx.x == 0) {
        int t = 0;
#pragma unroll
        for (int q = 0; q < 8; q++) t += sh[q];
        off = t;
    }
    __syncthreads();
    int i = b * 256 + threadIdx.x;
    if (i < NN) ptr[i] += off;
    if (b == gridDim.x - 1 && threadIdx.x == 0) ptr[NN] = off + bsum[b];
}

__global__ void fill_k(const int* __restrict__ dst, const int* __restrict__ ptr,
                       int* __restrict__ cursor, int* __restrict__ eidx) {
    int e = blockIdx.x * blockDim.x + threadIdx.x;
    if (e >= EE) return;
    int d = dst[e];
    int s = atomicAdd(&cursor[d], 1);
    eidx[ptr[d] + s] = e;
}

__global__ void gstart_k(const int* __restrict__ batch, int* __restrict__ gs) {
    int g = blockIdx.x * blockDim.x + threadIdx.x;
    if (g > GG) return;
    if (g == GG) { gs[GG] = NN; return; }
    int lo = 0, hi = NN;
    while (lo < hi) { int mid = (lo + hi) >> 1; if (batch[mid] < g) lo = mid + 1; else hi = mid; }
    gs[g] = lo;
}

// -------- gather aggregation: agg[n] = nw[n]*h[n] + sum_e eb[e]*nw[s]*h[s] --------
template <int D>
__global__ void gather_agg_k(const float* __restrict__ h, const int* __restrict__ ptr,
                             const int* __restrict__ eidx, const int* __restrict__ src,
                             const float* __restrict__ eb, const float* __restrict__ nw,
                             float* __restrict__ agg) {
    constexpr int TPN = D / 4;
    constexpr int NPB = 256 / TPN;
    int node = blockIdx.x * NPB + threadIdx.x / TPN;
    int lane = threadIdx.x % TPN;
    if (node >= NN) return;
    float sw = nw ? nw[node] : 1.f;
    float4 hv = *(const float4*)(h + (size_t)node * D + lane * 4);
    float4 acc = make_float4(hv.x * sw, hv.y * sw, hv.z * sw, hv.w * sw);
    int b = ptr[node], e = ptr[node + 1];
    for (int i = b; i < e; i++) {
        int id = eidx[i];
        int s = src[id];
        float w = (eb ? eb[id] : 1.f) * (nw ? nw[s] : 1.f);
        float4 v = *(const float4*)(h + (size_t)s * D + lane * 4);
        acc.x += v.x * w; acc.y += v.y * w; acc.z += v.z * w; acc.w += v.w * w;
    }
    *(float4*)(agg + (size_t)node * D + lane * 4) = acc;
}

// -------- pooling: aligned float4 reads, float2 writes (d_out safe) --------
__global__ void pool_g_k(const float* __restrict__ h, const int* __restrict__ gs,
                         float* __restrict__ gout) {
    int g = blockIdx.x, lane = threadIdx.x;  // 64 threads
    float4 acc = make_float4(0.f, 0.f, 0.f, 0.f);
    int b = gs[g], e = gs[g + 1];
    for (int n = b; n < e; n++) {
        float4 v = *(const float4*)(h + (size_t)n * DD + lane * 4);
        acc.x += v.x; acc.y += v.y; acc.z += v.z; acc.w += v.w;
    }
    float* o = gout + (size_t)g * DD + lane * 4;
    *(float2*)(o)     = make_float2(acc.x, acc.y);
    *(float2*)(o + 2) = make_float2(acc.z, acc.w);
}

// -------- fp32 GEMM 128x128x8, 8x8 microtile, double-buffered smem --------
#define GBM 128
#define GBN 128
#define GBK 8
__global__ __launch_bounds__(256, 2)
void gemm2_k(const float* __restrict__ A, const float* __restrict__ W,
             const float* __restrict__ bias, float* __restrict__ C,
             int M, int K, int Nout,
             const float* __restrict__ rowExtra, const int* __restrict__ rowIdx,
             int doRelu, float* __restrict__ C2) {
    __shared__ float As[2][GBK][GBM];
    __shared__ float Ws[2][GBK][GBN];
    int bm = blockIdx.y * GBM, bn = blockIdx.x * GBN;
    int tid = threadIdx.x;
    int ar = tid >> 1;
    int ac = (tid & 1) * 4;
    int wr = tid >> 5;
    int wc = (tid & 31) * 4;
    int tx = tid % 16, ty = tid / 16;
    int arow = bm + ar;
    const float* Ap = A + (size_t)arow * K + ac;
    const float* Wp = W + (size_t)wr * Nout + bn + wc;

    float4 av = (arow < M) ? *(const float4*)(Ap) : make_float4(0.f, 0.f, 0.f, 0.f);
    float4 wv = *(const float4*)(Wp);
    As[0][ac + 0][ar] = av.x; As[0][ac + 1][ar] = av.y;
    As[0][ac + 2][ar] = av.z; As[0][ac + 3][ar] = av.w;
    *(float4*)(&Ws[0][wr][wc]) = wv;
    __syncthreads();

    float acc[8][8] = {};
    int nk = K / GBK;
    for (int t = 0; t < nk; t++) {
        int buf = t & 1;
        if (t + 1 < nk) {
            av = (arow < M) ? *(const float4*)(Ap + (t + 1) * GBK)
                            : make_float4(0.f, 0.f, 0.f, 0.f);
            wv = *(const float4*)(Wp + (size_t)(t + 1) * GBK * Nout);
        }
#pragma unroll
        for (int kk = 0; kk < GBK; kk++) {
            float a[8], b[8];
            *(float4*)(a)     = *(const float4*)(&As[buf][kk][ty * 4]);
            *(float4*)(a + 4) = *(const float4*)(&As[buf][kk][64 + ty * 4]);
            *(float4*)(b)     = *(const float4*)(&Ws[buf][kk][tx * 4]);
            *(float4*)(b + 4) = *(const float4*)(&Ws[buf][kk][64 + tx * 4]);
#pragma unroll
            for (int i = 0; i < 8; i++)
#pragma unroll
                for (int j = 0; j < 8; j++) acc[i][j] += a[i] * b[j];
        }
        if (t + 1 < nk) {
            int nb_ = buf ^ 1;
            As[nb_][ac + 0][ar] = av.x; As[nb_][ac + 1][ar] = av.y;
            As[nb_][ac + 2][ar] = av.z; As[nb_][ac + 3][ar] = av.w;
            *(float4*)(&Ws[nb_][wr][wc]) = wv;
        }
        __syncthreads();
    }
#pragma unroll
    for (int i = 0; i < 8; i++) {
        int row = bm + (i < 4 ? ty * 4 + i : 64 + ty * 4 + i - 4);
        if (row >= M) continue;
        const float* ex = rowExtra ? rowExtra + (size_t)rowIdx[row] * Nout : nullptr;
#pragma unroll
        for (int j = 0; j < 8; j++) {
            int col = bn + (j < 4 ? tx * 4 + j : 64 + tx * 4 + j - 4);
            float v = acc[i][j] + bias[col];
            if (ex) v += ex[col];
            if (doRelu) v = fmaxf(v, 0.f);
            C[(size_t)row * Nout + col] = v;
            if (C2) C2[(size_t)row * Nout + col] = v;   // scalar store: d_out safe
        }
    }
}

// -------- cosine / prototype kernels --------
__global__ void rownorm_k(const float* __restrict__ v, float* __restrict__ out, int stride) {
    int r = blockIdx.x, lane = threadIdx.x;
    float s = 0.f;
#pragma unroll
    for (int q = 0; q < 8; q++) {
        float e = v[(size_t)r * stride + lane + q * 32];
        s += e * e;
    }
    s = warp_sum(s);
    float n = sqrtf(s);
    if (n == 0.f) n = EPSV;
    if (lane == 0) out[r] = n;
}

__global__ void cos_argmax_k(const float* __restrict__ gemb, const float* __restrict__ proto,
                             const float* __restrict__ pnorm, int* __restrict__ assign) {
    int g = blockIdx.x, lane = threadIdx.x;
    float ge[8];
    float ns = 0.f;
#pragma unroll
    for (int q = 0; q < 8; q++) {
        ge[q] = gemb[(size_t)g * DD + lane + q * 32];
        ns += ge[q] * ge[q];
    }
    ns = warp_sum(ns);
    float nrm = sqrtf(ns);
    if (nrm == 0.f) nrm = EPSV;
    float best = -1e30f;
    int bi = 0;
    for (int p = 0; p < PP; p++) {
        float d = 0.f;
#pragma unroll
        for (int q = 0; q < 8; q++) d += ge[q] * proto[(size_t)p * DD + lane + q * 32];
        d = warp_sum(d);
        float sim = d / (nrm * pnorm[p]);
        if (sim > best) { best = sim; bi = p; }
    }
    if (lane == 0) assign[g] = bi;
}

__global__ void nassign_k(const int* __restrict__ batch, const int* __restrict__ assign,
                          int* __restrict__ nassign) {
    int i = blockIdx.x * blockDim.x + threadIdx.x;
    if (i < NN) nassign[i] = assign[batch[i]];
}

__global__ void contrib_k(const float* __restrict__ proto, const float* __restrict__ Wm1,
                          float* __restrict__ contrib) {
    __shared__ float pr[DD];
    int p = blockIdx.x, tid = threadIdx.x;
    pr[tid] = proto[(size_t)p * DD + tid];
    __syncthreads();
    float a = 0.f;
    for (int k = 0; k < DD; k++) a += pr[k] * Wm1[(size_t)(DD + k) * DD + tid];
    contrib[(size_t)p * DD + tid] = a;
}

// node_prob -> sigmoid (+ fused node-KL accumulation). 8 warps/block, 1 node/warp.
__global__ void nodeprob_k(const float* __restrict__ hid, const float* __restrict__ Wm2,
                           const float* __restrict__ bm2, float* __restrict__ nb,
                           float* __restrict__ nbout, float* __restrict__ acc) {
    int w = blockIdx.x * 8 + (threadIdx.x >> 5);
    int lane = threadIdx.x & 31;
    __shared__ float sh[8];
    float term = 0.f;
    if (w < NN) {
        float d = 0.f;
#pragma unroll
        for (int q = 0; q < 8; q++) {
            int c = lane + q * 32;
            d += hid[(size_t)w * DD + c] * Wm2[c];
        }
        d = warp_sum(d);
        if (lane == 0) {
            float s = 1.f / (1.f + expf(-(d + bm2[0])));
            nb[w] = s; nbout[w] = s;
            term = s * logf(s / 0.5f + EPSV)
                 + (1.f - s) * logf((1.f - s) / (1.f - 0.5f + EPSV) + EPSV);
        }
    }
    if (lane == 0) sh[threadIdx.x >> 5] = term;
    __syncthreads();
    if (threadIdx.x == 0) {
        float t = 0.f;
#pragma unroll
        for (int q = 0; q < 8; q++) t += sh[q];
        atomicAdd(acc, t);
    }
}

// edge_bern (+ fused edge-KL accumulation)
__global__ void edgebern_k(const float* __restrict__ nb, const int* __restrict__ src,
                           const int* __restrict__ dst, float* __restrict__ out,
                           float* __restrict__ acc) {
    int i = blockIdx.x * blockDim.x + threadIdx.x;
    float term = 0.f;
    if (i < EE) {
        float v = nb[src[i]] * nb[dst[i]];
        out[i] = v;
        term = v * logf(v / 0.25f + EPSV)
             + (1.f - v) * logf((1.f - v) / (1.f - 0.25f + EPSV) + EPSV);
    }
    block_atomic_add(term, acc + 1);
}

__global__ void sim_nce_k(const float* __restrict__ semb, const float* __restrict__ gnorm,
                          const float* __restrict__ proto, const float* __restrict__ pnorm,
                          float* __restrict__ simout, float* __restrict__ acc) {
    int g = blockIdx.x, lane = threadIdx.x;
    float ge[8];
#pragma unroll
    for (int q = 0; q < 8; q++) ge[q] = semb[(size_t)g * DD + lane + q * 32];
    float nrm = gnorm[g];
    float best = -1e30f, pos = 0.f, sum = 0.f;
    for (int p = 0; p < PP; p++) {
        float d = 0.f;
#pragma unroll
        for (int q = 0; q < 8; q++) d += ge[q] * proto[(size_t)p * DD + lane + q * 32];
        d = warp_sum(d);
        float sim = d / (nrm * pnorm[p]);
        if (lane == 0) simout[(size_t)g * PP + p] = sim;
        float se = expf(sim / TEMPV);
        sum += se;
        if (sim > best) { best = sim; pos = se; }
    }
    if (lane == 0) atomicAdd(&acc[2], -logf(pos / (sum - pos)));
}

__global__ void datasim_k(const float* __restrict__ semb, const float* __restrict__ gnorm,
                          float* __restrict__ out) {
    __shared__ float ri[DD];
    int i = blockIdx.x, tid = threadIdx.x, lane = tid & 31, w = tid >> 5;
    ri[tid] = semb[(size_t)i * DD + tid];
    __syncthreads();
    float ni = gnorm[i];
    for (int j = w; j < GG; j += 8) {
        float d = 0.f;
#pragma unroll
        for (int q = 0; q < 8; q++) {
            int c = lane + q * 32;
            d += ri[c] * semb[(size_t)j * DD + c];
        }
        d = warp_sum(d);
        if (lane == 0) out[(size_t)i * GG + j] = d / (ni * gnorm[j]);
    }
}

__global__ void finalize_k(const float* __restrict__ acc, float* __restrict__ out) {
    if (threadIdx.x == 0) {
        out[O_KL]  = acc[0] / (float)NN + acc[1] / (float)EE;
        out[O_NCE] = acc[2] / (float)GG;
    }
}

// =====================================================================
extern "C" void kernel_launch(void* const* d_in, const int* in_sizes, int n_in,
                              void* d_out, int out_size) {
    const float* x    = (const float*)d_in[0];
    const int*   ei   = (const int*)d_in[1];
    const int*   bat  = (const int*)d_in[2];
    const float* W1   = (const float*)d_in[3];
    const float* b1   = (const float*)d_in[4];
    const float* W2   = (const float*)d_in[5];
    const float* b2   = (const float*)d_in[6];
    const float* Wm1  = (const float*)d_in[7];
    const float* bm1  = (const float*)d_in[8];
    const float* Wm2  = (const float*)d_in[9];
    const float* bm2  = (const float*)d_in[10];
    const float* prot = (const float*)d_in[11];
    float* out = (float*)d_out;

    const int* src = ei;
    const int* dst = ei + EE;

    float *agg, *h1, *h2, *hid, *gemb, *pnorm, *gnorm, *contrib, *nb, *acc;
    int *assign, *nassign, *cnt, *ptr, *cursor, *eidx, *gstart, *bsum;
    cudaGetSymbolAddress((void**)&agg, g_agg);
    cudaGetSymbolAddress((void**)&h1, g_h1);
    cudaGetSymbolAddress((void**)&h2, g_h2);
    cudaGetSymbolAddress((void**)&hid, g_hid);
    cudaGetSymbolAddress((void**)&gemb, g_gemb);
    cudaGetSymbolAddress((void**)&pnorm, g_pnorm);
    cudaGetSymbolAddress((void**)&gnorm, g_gnorm);
    cudaGetSymbolAddress((void**)&contrib, g_contrib);
    cudaGetSymbolAddress((void**)&nb, g_nb);
    cudaGetSymbolAddress((void**)&acc, g_acc);
    cudaGetSymbolAddress((void**)&assign, g_assign);
    cudaGetSymbolAddress((void**)&nassign, g_nassign);
    cudaGetSymbolAddress((void**)&cnt, g_cnt);
    cudaGetSymbolAddress((void**)&ptr, g_ptr);
    cudaGetSymbolAddress((void**)&cursor, g_cursor);
    cudaGetSymbolAddress((void**)&eidx, g_eidx);
    cudaGetSymbolAddress((void**)&gstart, g_gstart);
    cudaGetSymbolAddress((void**)&bsum, g_bsum);

    const int T = 256;
    auto blks = [](long n, int t) { return (int)((n + t - 1) / t); };

    // ---- CSR build ----
    zero_misc_k<<<blks(NN, T), T>>>(cnt, cursor, acc);
    hist_k<<<blks(EE, T), T>>>(dst, cnt);
    scan1_k<<<SCAN_B, 256>>>(cnt, ptr, bsum);
    scan2_k<<<SCAN_B, 256>>>(ptr, bsum);
    fill_k<<<blks(EE, T), T>>>(dst, ptr, cursor, eidx);
    gstart_k<<<1, GG + 1>>>(bat, gstart);

    dim3 gg(DD / GBN, (NN + GBM - 1) / GBM);

    // ---- pass 1 ----
    gather_agg_k<INF><<<blks(NN, 8), 256>>>(x, ptr, eidx, src, nullptr, nullptr, agg);
    gemm2_k<<<gg, 256>>>(agg, W1, b1, h1, NN, INF, DD, nullptr, nullptr, 1, nullptr);
    gather_agg_k<DD><<<blks(NN, 4), 256>>>(h1, ptr, eidx, src, nullptr, nullptr, agg);
    gemm2_k<<<gg, 256>>>(agg, W2, b2, h2, NN, DD, DD, nullptr, nullptr, 1, out + O_NE);
    pool_g_k<<<GG, 64>>>(h2, gstart, gemb);

    // prototype assignment
    rownorm_k<<<PP, 32>>>(prot, pnorm, DD);
    cos_argmax_k<<<GG, 32>>>(gemb, prot, pnorm, assign);
    nassign_k<<<blks(NN, T), T>>>(bat, assign, nassign);

    // MLP
    contrib_k<<<PP, DD>>>(prot, Wm1, contrib);
    gemm2_k<<<gg, 256>>>(h2, Wm1, bm1, hid, NN, DD, DD, contrib, nassign, 1, nullptr);
    nodeprob_k<<<blks(NN, 8), 256>>>(hid, Wm2, bm2, nb, out + O_NB, acc);
    edgebern_k<<<blks(EE, T), T>>>(nb, src, dst, out + O_EB, acc);

    // ---- pass 2 (attenuated; x2 folded into gather via node weight nb) ----
    gather_agg_k<INF><<<blks(NN, 8), 256>>>(x, ptr, eidx, src, out + O_EB, nb, agg);
    gemm2_k<<<gg, 256>>>(agg, W1, b1, h1, NN, INF, DD, nullptr, nullptr, 1, nullptr);
    gather_agg_k<DD><<<blks(NN, 4), 256>>>(h1, ptr, eidx, src, out + O_EB, nullptr, agg);
    gemm2_k<<<gg, 256>>>(agg, W2, b2, hid, NN, DD, DD, nullptr, nullptr, 1, nullptr);
    pool_g_k<<<GG, 64>>>(hid, gstart, out + O_SE);

    rownorm_k<<<GG, 32>>>(out + O_SE, gnorm, DD);
    sim_nce_k<<<GG, 32>>>(out + O_SE, gnorm, prot, pnorm, out + O_SIM, acc);
    datasim_k<<<GG, DD>>>(out + O_SE, gnorm, out + O_DS);

    finalize_k<<<1, 32>>>(acc, out);
}